// round 16
// baseline (speedup 1.0000x reference)
#include <cuda_runtime.h>
#include <cuda_bf16.h>
#include <cstdint>

#define NPTS 8            // points per CTA
#define TPB 256           // 8 warps

// ---- SMEM layout (byte offsets from 1024-aligned base) ----
// A' transposed [k][m], m-row = ch*8 + p  (6 ch x 8 pts = 48 rows), 112B row stride
#define ASTR_T  112
#define OFF_AHI 0         // 256*112 = 28672
#define OFF_ALO 28672     // ends 57344
#define OFF_B   57344     // 3 x chunk buffers of 16896 B
#define BUF_BYTES 16896
#define BSPL    8448
#define BSTR    528
#define OFF_RED 57344     // final-reduction scratch (aliases buffers; used only at the end)
#define OFF_MBAR 108032   // F[3]@+0, E[3]@+24, W[8]@+48, R[8]@+112
#define SMEM_BYTES (108032 + 256 + 1024)   // 109312 -> 2 CTAs/SM

// weights staged in EXACT smem-image layout: [layer][chunk16][split2][16 rows x 528B]
__device__ __align__(16) unsigned char g_Wstage[3 * 16 * BUF_BYTES];

#define LDSM4T(R0,R1,R2,R3,ADDR) \
  asm volatile("ldmatrix.sync.aligned.m8n8.x4.trans.shared.b16 {%0,%1,%2,%3}, [%4];" \
    : "=r"(R0),"=r"(R1),"=r"(R2),"=r"(R3) : "r"(ADDR))
#define MMA_BF16(D,A0,A1,A2,A3,B0,B1) \
  asm volatile("mma.sync.aligned.m16n8k16.row.col.f32.bf16.bf16.f32 " \
    "{%0,%1,%2,%3},{%4,%5,%6,%7},{%8,%9},{%0,%1,%2,%3};" \
    : "+f"(D[0]),"+f"(D[1]),"+f"(D[2]),"+f"(D[3]) \
    : "r"(A0),"r"(A1),"r"(A2),"r"(A3),"r"(B0),"r"(B1))

#define MBAR_INIT(ADDR, CNT) \
  asm volatile("mbarrier.init.shared.b64 [%0], %1;" :: "r"(ADDR), "r"(CNT) : "memory")
#define MBAR_EXPECT_TX(ADDR, BYTES) \
  asm volatile("mbarrier.arrive.expect_tx.shared.b64 _, [%0], %1;" :: "r"(ADDR), "r"(BYTES) : "memory")
#define MBAR_ARRIVE(ADDR) \
  asm volatile("mbarrier.arrive.shared.b64 _, [%0];" :: "r"(ADDR) : "memory")
#define BULK_LOAD(DST, SRC, BYTES, MBAR) \
  asm volatile("cp.async.bulk.shared::cluster.global.mbarrier::complete_tx::bytes [%0], [%1], %2, [%3];" \
    :: "r"(DST), "l"(SRC), "r"(BYTES), "r"(MBAR) : "memory")
#define MBAR_WAIT(ADDR, PAR) do { \
    asm volatile( \
        "{\n\t.reg .pred P;\n" \
        "WL%=:\n\t" \
        "mbarrier.try_wait.parity.acquire.cta.shared::cta.b64 P, [%0], %1, 0x989680;\n\t" \
        "@P bra WD%=;\n\t" \
        "bra WL%=;\n" \
        "WD%=:\n\t}" \
        :: "r"(ADDR), "r"(PAR) : "memory"); \
} while (0)

__device__ __forceinline__ uint32_t smem_u32(const void* p) {
    uint32_t a;
    asm("{ .reg .u64 t; cvta.to.shared.u64 t, %1; cvt.u32.u64 %0, t; }" : "=r"(a) : "l"(p));
    return a;
}

__device__ __forceinline__ void swish_derivs(float z, float& s, float& sp, float& spp) {
    float sig = 1.0f / (1.0f + __expf(-z));
    float om  = 1.0f - sig;
    s   = z * sig;
    sp  = sig * (1.0f + z * om);
    spp = sig * om * (2.0f + z * (1.0f - 2.0f * sig));
}

__device__ __forceinline__ void split_pack(float a, float b, uint32_t& hp, uint32_t& lp) {
    __nv_bfloat16 ha = __float2bfloat16(a);
    __nv_bfloat16 hb = __float2bfloat16(b);
    __nv_bfloat16 la = __float2bfloat16(a - __bfloat162float(ha));
    __nv_bfloat16 lb = __float2bfloat16(b - __bfloat162float(hb));
    uint16_t uha = *reinterpret_cast<uint16_t*>(&ha);
    uint16_t uhb = *reinterpret_cast<uint16_t*>(&hb);
    uint16_t ula = *reinterpret_cast<uint16_t*>(&la);
    uint16_t ulb = *reinterpret_cast<uint16_t*>(&lb);
    hp = (uint32_t)uha | ((uint32_t)uhb << 16);
    lp = (uint32_t)ula | ((uint32_t)ulb << 16);
}

// single-value hi/lo store into A' at column k, m-row = ch*8+p
__device__ __forceinline__ void storeA1(char* sm, int k, int p, int ch, float v) {
    const uint32_t o = (uint32_t)k * ASTR_T + (uint32_t)(ch * 8 + p) * 2;
    __nv_bfloat16 hi = __float2bfloat16(v);
    __nv_bfloat16 lo = __float2bfloat16(v - __bfloat162float(hi));
    *reinterpret_cast<uint16_t*>(sm + OFF_AHI + o) = *reinterpret_cast<uint16_t*>(&hi);
    *reinterpret_cast<uint16_t*>(sm + OFF_ALO + o) = *reinterpret_cast<uint16_t*>(&lo);
}

// ---- prep: split W1..W3 into bf16 hi/lo, stored in smem-image chunk layout ----
__global__ void prep_kernel(const float* __restrict__ W1, const float* __restrict__ W2,
                            const float* __restrict__ W3) {
    int i = blockIdx.x * blockDim.x + threadIdx.x;
    if (i >= 3 * 65536) return;
    const int layer = i >> 16;
    const int r = i & 65535;
    const int k = r >> 8;
    const int n = r & 255;
    const float* W = (layer == 0) ? W1 : (layer == 1) ? W2 : W3;
    const float w = W[r];
    __nv_bfloat16 hi = __float2bfloat16(w);
    float rem = w - __bfloat162float(hi);
    __nv_bfloat16 lo = __float2bfloat16(rem);
    const int chunk = k >> 4;
    const int kr = k & 15;
    const size_t base = (size_t)(layer * 16 + chunk) * BUF_BYTES + (size_t)kr * BSTR + (size_t)n * 2;
    *reinterpret_cast<__nv_bfloat16*>(g_Wstage + base) = hi;
    *reinterpret_cast<__nv_bfloat16*>(g_Wstage + base + BSPL) = lo;
}

// producer: fill global-chunk g into buffer g%3 (waits buffer-empty for rounds >= 1)
__device__ __forceinline__ void issue_fill(uint32_t sbase, int g) {
    const uint32_t mbf = sbase + OFF_MBAR + (uint32_t)(g % 3) * 8;
    const uint32_t mbe = sbase + OFF_MBAR + 24 + (uint32_t)(g % 3) * 8;
    const int r = g / 3;
    if (r >= 1) MBAR_WAIT(mbe, (uint32_t)((r - 1) & 1));
    MBAR_EXPECT_TX(mbf, (uint32_t)BUF_BYTES);
    BULK_LOAD(sbase + OFF_B + (uint32_t)(g % 3) * BUF_BYTES,
              (const void*)(g_Wstage + (size_t)g * BUF_BYTES),
              (uint32_t)BUF_BYTES, mbf);
}

// ---- main kernel ----
__global__ __launch_bounds__(TPB, 2)
void pinn_mma_kernel(
    const float* __restrict__ x, const float* __restrict__ y,
    const float* __restrict__ t, const float* __restrict__ nu,
    const float* __restrict__ W0, const float* __restrict__ b0,
    const float* __restrict__ b1, const float* __restrict__ b2,
    const float* __restrict__ b3,
    const float* __restrict__ W4, const float* __restrict__ b4,
    float* __restrict__ out, int N)
{
    extern __shared__ char smem_raw[];
    const uint32_t rawa = smem_u32(smem_raw);
    const uint32_t sbase = (rawa + 1023u) & ~1023u;
    char* sm = smem_raw + (sbase - rawa);

    const int tid  = threadIdx.x;
    const int wid  = tid >> 5;
    const int lane = tid & 31;
    const int base = blockIdx.x * NPTS;

    const int n0 = wid * 32;         // N group start (32 cols per warp) == A'-region wid
    const int nn = tid;              // neuron (0..255) for layer0
    const int pp = lane >> 2;        // this thread's point (epilogue)

    const uint32_t mbarF = sbase + OFF_MBAR;
    const uint32_t mbarE = sbase + OFF_MBAR + 24;
    const uint32_t mbarW = sbase + OFF_MBAR + 48;    // W[8]: region written (count 1)
    const uint32_t mbarR = sbase + OFF_MBAR + 112;   // R[8]: region read-done (count 8)

    if (tid == 0) {
        #pragma unroll
        for (int i = 0; i < 3; i++) {
            MBAR_INIT(mbarF + (uint32_t)i * 8, 1u);
            MBAR_INIT(mbarE + (uint32_t)i * 8, 8u);
        }
        #pragma unroll
        for (int i = 0; i < 8; i++) {
            MBAR_INIT(mbarW + (uint32_t)i * 8, 1u);
            MBAR_INIT(mbarR + (uint32_t)i * 8, 8u);
        }
    }
    __syncthreads();

    if (tid == 0) { issue_fill(sbase, 0); issue_fill(sbase, 1); }

    // ---------------- layer 0: (4 -> 256) scalar -> A' row nn ----------------
    // row within A' column: m = ch*8 + p ; warp wid writes k-region wid
    {
        const float w0 = W0[nn], w1 = W0[256 + nn], w2 = W0[512 + nn], w3 = W0[768 + nn];
        const float bb = b0[nn];
        float o[6][NPTS];
        #pragma unroll
        for (int p = 0; p < NPTS; p++) {
            int idx = base + p; if (idx >= N) idx = N - 1;
            const float xs = x[idx];
            const float ys = y[idx];
            const float ts = 2.0f * t[idx] - 1.0f;
            const float ns = 2.0f * (nu[idx] - 0.01f) * (1.0f / 0.09f) - 1.0f;
            const float z  = fmaf(xs, w0, fmaf(ys, w1, fmaf(ts, w2, fmaf(ns, w3, bb))));
            const float zx = w0, zy = w1, zt = 2.0f * w2;
            float s, sp, spp; swish_derivs(z, s, sp, spp);
            o[0][p] = s;
            o[1][p] = sp * zx;
            o[2][p] = sp * zy;
            o[3][p] = sp * zt;
            o[4][p] = spp * zx * zx;
            o[5][p] = spp * zy * zy;
        }
        uint32_t h32[24], l32[24];
        #pragma unroll
        for (int ch = 0; ch < 6; ch++)
            #pragma unroll
            for (int q = 0; q < 4; q++)
                split_pack(o[ch][2 * q], o[ch][2 * q + 1], h32[ch * 4 + q], l32[ch * 4 + q]);
        uint4* dh = reinterpret_cast<uint4*>(sm + OFF_AHI + nn * ASTR_T);
        uint4* dl = reinterpret_cast<uint4*>(sm + OFF_ALO + nn * ASTR_T);
        #pragma unroll
        for (int j = 0; j < 6; j++) {
            dh[j] = make_uint4(h32[4*j], h32[4*j+1], h32[4*j+2], h32[4*j+3]);
            dl[j] = make_uint4(l32[4*j], l32[4*j+1], l32[4*j+2], l32[4*j+3]);
        }
        __syncwarp();
        if (lane == 0) MBAR_ARRIVE(mbarW + (uint32_t)wid * 8);   // region wid written (A0)
    }

    // final-layer partial accumulators (used at L==2)
    float part[12];   // [ch][uv]
    #pragma unroll
    for (int r = 0; r < 12; r++) part[r] = 0.0f;

    // ---------------- 3 hidden layers: bf16-split GEMM + register swish -----
    #pragma unroll 1
    for (int L = 0; L < 3; L++) {
        const float* __restrict__ bptr = (L == 0) ? b1 : (L == 1) ? b2 : b3;
        const uint32_t lpar = (uint32_t)(L & 1);

        float acc[3][4][4];
        #pragma unroll
        for (int m = 0; m < 3; m++)
            #pragma unroll
            for (int nt = 0; nt < 4; nt++)
                #pragma unroll
                for (int r = 0; r < 4; r++) acc[m][nt][r] = 0.0f;

        #pragma unroll 1
        for (int c = 0; c < 16; c++) {
            const int g = L * 16 + c;
            if (tid == 0 && g + 2 < 48) issue_fill(sbase, g + 2);

            MBAR_WAIT(mbarF + (uint32_t)(g % 3) * 8, (uint32_t)((g / 3) & 1));

            const uint32_t bufb = sbase + OFF_B + (uint32_t)(g % 3) * BUF_BYTES;

            uint32_t Bh[8], Bl[8];
            #pragma unroll
            for (int q = 0; q < 2; q++) {
                const uint32_t roff = (uint32_t)(lane & 15) * BSTR
                                    + (uint32_t)(n0 + q * 16 + (lane >> 4) * 8) * 2;
                LDSM4T(Bh[q * 4], Bh[q * 4 + 1], Bh[q * 4 + 2], Bh[q * 4 + 3], bufb + roff);
                LDSM4T(Bl[q * 4], Bl[q * 4 + 1], Bl[q * 4 + 2], Bl[q * 4 + 3], bufb + BSPL + roff);
            }
            if (lane == 0) MBAR_ARRIVE(mbarE + (uint32_t)(g % 3) * 8);

            // A'-region (c>>1) must be written for this layer before A-LDSM
            if ((c & 1) == 0) MBAR_WAIT(mbarW + (uint32_t)(c >> 1) * 8, lpar);

            uint32_t Ah[3][4];
            uint32_t aroff[3];
            const uint32_t krow = (uint32_t)(c * 16 + (lane & 7) + ((lane >> 4) << 3));
            const uint32_t mcol = (uint32_t)(((lane >> 3) & 1) * 8) * 2;
            #pragma unroll
            for (int m = 0; m < 3; m++) {
                aroff[m] = krow * ASTR_T + (uint32_t)(m * 16) * 2 + mcol;
                LDSM4T(Ah[m][0], Ah[m][1], Ah[m][2], Ah[m][3], sbase + OFF_AHI + aroff[m]);
            }
            #pragma unroll
            for (int m = 0; m < 3; m++)
                #pragma unroll
                for (int nt = 0; nt < 4; nt++)
                    MMA_BF16(acc[m][nt], Ah[m][0], Ah[m][1], Ah[m][2], Ah[m][3],
                             Bh[nt * 2], Bh[nt * 2 + 1]);
            #pragma unroll
            for (int m = 0; m < 3; m++)
                #pragma unroll
                for (int nt = 0; nt < 4; nt++)
                    MMA_BF16(acc[m][nt], Ah[m][0], Ah[m][1], Ah[m][2], Ah[m][3],
                             Bl[nt * 2], Bl[nt * 2 + 1]);
            uint32_t Al[3][4];
            #pragma unroll
            for (int m = 0; m < 3; m++)
                LDSM4T(Al[m][0], Al[m][1], Al[m][2], Al[m][3], sbase + OFF_ALO + aroff[m]);
            // last A-read of region (c>>1) for this layer done at odd c
            if (c & 1) {
                __syncwarp();
                if (lane == 0) MBAR_ARRIVE(mbarR + (uint32_t)(c >> 1) * 8);
            }
            #pragma unroll
            for (int m = 0; m < 3; m++)
                #pragma unroll
                for (int nt = 0; nt < 4; nt++)
                    MMA_BF16(acc[m][nt], Al[m][0], Al[m][1], Al[m][2], Al[m][3],
                             Bh[nt * 2], Bh[nt * 2 + 1]);
        }

        // ---- register epilogue: swish chain straight from accumulators ----
        if (L < 2) {
            // wait: all warps done reading my region this layer
            MBAR_WAIT(mbarR + (uint32_t)wid * 8, lpar);
            #pragma unroll
            for (int nt = 0; nt < 4; nt++) {
                const int k0 = n0 + nt * 8 + (lane & 3) * 2;
                const float2 bv = *reinterpret_cast<const float2*>(&bptr[k0]);
                #pragma unroll
                for (int j = 0; j < 2; j++) {
                    const int k = k0 + j;
                    const float z   = acc[0][nt][j] + (j ? bv.y : bv.x);
                    const float zx  = acc[0][nt][2 + j];
                    const float zy  = acc[1][nt][j];
                    const float zt  = acc[1][nt][2 + j];
                    const float zxx = acc[2][nt][j];
                    const float zyy = acc[2][nt][2 + j];
                    float s, sp, spp; swish_derivs(z, s, sp, spp);
                    storeA1(sm, k, pp, 0, s);
                    storeA1(sm, k, pp, 1, sp * zx);
                    storeA1(sm, k, pp, 2, sp * zy);
                    storeA1(sm, k, pp, 3, sp * zt);
                    storeA1(sm, k, pp, 4, fmaf(spp, zx * zx, sp * zxx));
                    storeA1(sm, k, pp, 5, fmaf(spp, zy * zy, sp * zyy));
                }
            }
            __syncwarp();
            if (lane == 0) MBAR_ARRIVE(mbarW + (uint32_t)wid * 8);   // region rewritten
        } else {
            // final layer: accumulate partial dots with W4 directly (no A' write)
            #pragma unroll
            for (int nt = 0; nt < 4; nt++) {
                const int k0 = n0 + nt * 8 + (lane & 3) * 2;
                const float2 bv = *reinterpret_cast<const float2*>(&bptr[k0]);
                #pragma unroll
                for (int j = 0; j < 2; j++) {
                    const int k = k0 + j;
                    const float z   = acc[0][nt][j] + (j ? bv.y : bv.x);
                    const float zx  = acc[0][nt][2 + j];
                    const float zy  = acc[1][nt][j];
                    const float zt  = acc[1][nt][2 + j];
                    const float zxx = acc[2][nt][j];
                    const float zyy = acc[2][nt][2 + j];
                    float s, sp, spp; swish_derivs(z, s, sp, spp);
                    const float o0 = s;
                    const float o1 = sp * zx;
                    const float o2 = sp * zy;
                    const float o3 = sp * zt;
                    const float o4 = fmaf(spp, zx * zx, sp * zxx);
                    const float o5 = fmaf(spp, zy * zy, sp * zyy);
                    const float2 w = *reinterpret_cast<const float2*>(&W4[2 * k]);
                    part[0]  = fmaf(o0, w.x, part[0]);   part[1]  = fmaf(o0, w.y, part[1]);
                    part[2]  = fmaf(o1, w.x, part[2]);   part[3]  = fmaf(o1, w.y, part[3]);
                    part[4]  = fmaf(o2, w.x, part[4]);   part[5]  = fmaf(o2, w.y, part[5]);
                    part[6]  = fmaf(o3, w.x, part[6]);   part[7]  = fmaf(o3, w.y, part[7]);
                    part[8]  = fmaf(o4, w.x, part[8]);   part[9]  = fmaf(o4, w.y, part[9]);
                    part[10] = fmaf(o5, w.x, part[10]);  part[11] = fmaf(o5, w.y, part[11]);
                }
            }
        }
    }

    __syncthreads();   // all warps done with B buffers; red (aliased) may be written

    // ---------------- final reduction: quad shuffles + smem ------------------
    #pragma unroll
    for (int r = 0; r < 12; r++) {
        part[r] += __shfl_xor_sync(0xffffffffu, part[r], 1);
        part[r] += __shfl_xor_sync(0xffffffffu, part[r], 2);
    }
    float* red = reinterpret_cast<float*>(sm + OFF_RED);   // [8 warps][8 pts][12]
    if ((lane & 3) == 0) {
        float* dst = red + (wid * 8 + pp) * 12;
        #pragma unroll
        for (int r = 0; r < 12; r++) dst[r] = part[r];
    }
    __syncthreads();

    if (tid < 96) {
        const int p = tid / 12, r = tid % 12;
        float s = 0.0f;
        #pragma unroll
        for (int w = 0; w < 8; w++) s += red[(w * 8 + p) * 12 + r];
        red[768 + p * 12 + r] = s;
    }
    __syncthreads();

    if (tid < NPTS) {
        const int idx = base + tid;
        if (idx < N) {
            const float* rp = red + 768 + tid * 12;
            const float u   = rp[0] + b4[0];
            const float v   = rp[1] + b4[1];
            const float u_x = rp[2],  v_x = rp[3];
            const float u_y = rp[4],  v_y = rp[5];
            const float u_t = rp[6],  v_t = rp[7];
            const float uxx = rp[8],  vxx = rp[9];
            const float uyy = rp[10], vyy = rp[11];
            const float nv = nu[idx];
            out[idx * 2 + 0] = u_t + u * u_x + v * u_y - nv * (uxx + uyy);
            out[idx * 2 + 1] = v_t + u * v_x + v * v_y - nv * (vxx + vyy);
        }
    }
}

extern "C" void kernel_launch(void* const* d_in, const int* in_sizes, int n_in,
                              void* d_out, int out_size) {
    const float* x  = (const float*)d_in[0];
    const float* y  = (const float*)d_in[1];
    const float* t  = (const float*)d_in[2];
    const float* nu = (const float*)d_in[3];
    const float* W0 = (const float*)d_in[4];
    const float* b0 = (const float*)d_in[5];
    const float* W1 = (const float*)d_in[6];
    const float* b1 = (const float*)d_in[7];
    const float* W2 = (const float*)d_in[8];
    const float* b2 = (const float*)d_in[9];
    const float* W3 = (const float*)d_in[10];
    const float* b3 = (const float*)d_in[11];
    const float* W4 = (const float*)d_in[12];
    const float* b4 = (const float*)d_in[13];
    float* out = (float*)d_out;

    const int N = in_sizes[0];

    cudaFuncSetAttribute(pinn_mma_kernel, cudaFuncAttributeMaxDynamicSharedMemorySize, SMEM_BYTES);

    prep_kernel<<<(3 * 65536 + 255) / 256, 256>>>(W1, W2, W3);

    const int blocks = (N + NPTS - 1) / NPTS;
    pinn_mma_kernel<<<blocks, TPB, SMEM_BYTES>>>(x, y, t, nu, W0, b0,
                                                 b1, b2, b3, W4, b4, out, N);
}

// round 17
// speedup vs baseline: 1.1010x; 1.1010x over previous
#include <cuda_runtime.h>
#include <cuda_bf16.h>
#include <cstdint>

#define NPTS 8            // points per CTA
#define TPB 256           // 8 warps

// ---- SMEM layout (byte offsets from 1024-aligned base) ----
// A' transposed [k][m], m-row = ch*8 + p  (6 ch x 8 pts = 48 rows), 112B row stride
#define ASTR_T  112
#define OFF_AHI 0         // 256*112 = 28672
#define OFF_ALO 28672     // ends 57344
#define OFF_B   57344     // 3 x chunk buffers of 16896 B
#define BUF_BYTES 16896
#define BSPL    8448
#define BSTR    528
#define OFF_RED 57344     // final-reduction scratch (aliases buffers; used only at the end)
#define OFF_MBAR 108032
#define SMEM_BYTES (108032 + 64 + 1024)   // -> 2 CTAs/SM

// weights staged in EXACT smem-image layout: [layer][chunk16][split2][16 rows x 528B]
__device__ __align__(16) unsigned char g_Wstage[3 * 16 * BUF_BYTES];

#define LDSM4T(R0,R1,R2,R3,ADDR) \
  asm volatile("ldmatrix.sync.aligned.m8n8.x4.trans.shared.b16 {%0,%1,%2,%3}, [%4];" \
    : "=r"(R0),"=r"(R1),"=r"(R2),"=r"(R3) : "r"(ADDR))
#define MMA_BF16(D,A0,A1,A2,A3,B0,B1) \
  asm volatile("mma.sync.aligned.m16n8k16.row.col.f32.bf16.bf16.f32 " \
    "{%0,%1,%2,%3},{%4,%5,%6,%7},{%8,%9},{%0,%1,%2,%3};" \
    : "+f"(D[0]),"+f"(D[1]),"+f"(D[2]),"+f"(D[3]) \
    : "r"(A0),"r"(A1),"r"(A2),"r"(A3),"r"(B0),"r"(B1))

#define MBAR_INIT(ADDR, CNT) \
  asm volatile("mbarrier.init.shared.b64 [%0], %1;" :: "r"(ADDR), "r"(CNT) : "memory")
#define MBAR_EXPECT_TX(ADDR, BYTES) \
  asm volatile("mbarrier.arrive.expect_tx.shared.b64 _, [%0], %1;" :: "r"(ADDR), "r"(BYTES) : "memory")
#define MBAR_ARRIVE(ADDR) \
  asm volatile("mbarrier.arrive.shared.b64 _, [%0];" :: "r"(ADDR) : "memory")
#define BULK_LOAD(DST, SRC, BYTES, MBAR) \
  asm volatile("cp.async.bulk.shared::cluster.global.mbarrier::complete_tx::bytes [%0], [%1], %2, [%3];" \
    :: "r"(DST), "l"(SRC), "r"(BYTES), "r"(MBAR) : "memory")
#define MBAR_WAIT(ADDR, PAR) do { \
    asm volatile( \
        "{\n\t.reg .pred P;\n" \
        "WL%=:\n\t" \
        "mbarrier.try_wait.parity.acquire.cta.shared::cta.b64 P, [%0], %1, 0x989680;\n\t" \
        "@P bra WD%=;\n\t" \
        "bra WL%=;\n" \
        "WD%=:\n\t}" \
        :: "r"(ADDR), "r"(PAR) : "memory"); \
} while (0)

__device__ __forceinline__ uint32_t smem_u32(const void* p) {
    uint32_t a;
    asm("{ .reg .u64 t; cvta.to.shared.u64 t, %1; cvt.u32.u64 %0, t; }" : "=r"(a) : "l"(p));
    return a;
}

__device__ __forceinline__ void swish_derivs(float z, float& s, float& sp, float& spp) {
    float sig = 1.0f / (1.0f + __expf(-z));
    float om  = 1.0f - sig;
    s   = z * sig;
    sp  = sig * (1.0f + z * om);
    spp = sig * om * (2.0f + z * (1.0f - 2.0f * sig));
}

__device__ __forceinline__ void split_pack(float a, float b, uint32_t& hp, uint32_t& lp) {
    __nv_bfloat16 ha = __float2bfloat16(a);
    __nv_bfloat16 hb = __float2bfloat16(b);
    __nv_bfloat16 la = __float2bfloat16(a - __bfloat162float(ha));
    __nv_bfloat16 lb = __float2bfloat16(b - __bfloat162float(hb));
    uint16_t uha = *reinterpret_cast<uint16_t*>(&ha);
    uint16_t uhb = *reinterpret_cast<uint16_t*>(&hb);
    uint16_t ula = *reinterpret_cast<uint16_t*>(&la);
    uint16_t ulb = *reinterpret_cast<uint16_t*>(&lb);
    hp = (uint32_t)uha | ((uint32_t)uhb << 16);
    lp = (uint32_t)ula | ((uint32_t)ulb << 16);
}

// single-value hi/lo store into A' at column k, m-row = ch*8+p
__device__ __forceinline__ void storeA1(char* sm, int k, int p, int ch, float v) {
    const uint32_t o = (uint32_t)k * ASTR_T + (uint32_t)(ch * 8 + p) * 2;
    __nv_bfloat16 hi = __float2bfloat16(v);
    __nv_bfloat16 lo = __float2bfloat16(v - __bfloat162float(hi));
    *reinterpret_cast<uint16_t*>(sm + OFF_AHI + o) = *reinterpret_cast<uint16_t*>(&hi);
    *reinterpret_cast<uint16_t*>(sm + OFF_ALO + o) = *reinterpret_cast<uint16_t*>(&lo);
}

// ---- prep: split W1..W3 into bf16 hi/lo, stored in smem-image chunk layout ----
__global__ void prep_kernel(const float* __restrict__ W1, const float* __restrict__ W2,
                            const float* __restrict__ W3) {
    int i = blockIdx.x * blockDim.x + threadIdx.x;
    if (i >= 3 * 65536) return;
    const int layer = i >> 16;
    const int r = i & 65535;
    const int k = r >> 8;
    const int n = r & 255;
    const float* W = (layer == 0) ? W1 : (layer == 1) ? W2 : W3;
    const float w = W[r];
    __nv_bfloat16 hi = __float2bfloat16(w);
    float rem = w - __bfloat162float(hi);
    __nv_bfloat16 lo = __float2bfloat16(rem);
    const int chunk = k >> 4;
    const int kr = k & 15;
    const size_t base = (size_t)(layer * 16 + chunk) * BUF_BYTES + (size_t)kr * BSTR + (size_t)n * 2;
    *reinterpret_cast<__nv_bfloat16*>(g_Wstage + base) = hi;
    *reinterpret_cast<__nv_bfloat16*>(g_Wstage + base + BSPL) = lo;
}

// producer: fill global-chunk g into buffer g%3 (waits buffer-empty for rounds >= 1)
__device__ __forceinline__ void issue_fill(uint32_t sbase, int g) {
    const uint32_t mbf = sbase + OFF_MBAR + (uint32_t)(g % 3) * 8;
    const uint32_t mbe = sbase + OFF_MBAR + 24 + (uint32_t)(g % 3) * 8;
    const int r = g / 3;
    if (r >= 1) MBAR_WAIT(mbe, (uint32_t)((r - 1) & 1));
    MBAR_EXPECT_TX(mbf, (uint32_t)BUF_BYTES);
    BULK_LOAD(sbase + OFF_B + (uint32_t)(g % 3) * BUF_BYTES,
              (const void*)(g_Wstage + (size_t)g * BUF_BYTES),
              (uint32_t)BUF_BYTES, mbf);
}

// ---- main kernel ----
__global__ __launch_bounds__(TPB, 2)
void pinn_mma_kernel(
    const float* __restrict__ x, const float* __restrict__ y,
    const float* __restrict__ t, const float* __restrict__ nu,
    const float* __restrict__ W0, const float* __restrict__ b0,
    const float* __restrict__ b1, const float* __restrict__ b2,
    const float* __restrict__ b3,
    const float* __restrict__ W4, const float* __restrict__ b4,
    float* __restrict__ out, int N)
{
    extern __shared__ char smem_raw[];
    const uint32_t rawa = smem_u32(smem_raw);
    const uint32_t sbase = (rawa + 1023u) & ~1023u;
    char* sm = smem_raw + (sbase - rawa);

    const int tid  = threadIdx.x;
    const int wid  = tid >> 5;
    const int lane = tid & 31;
    const int base = blockIdx.x * NPTS;

    const int n0 = wid * 32;         // N group start (32 cols per warp)
    const int nn = tid;              // neuron (0..255) for layer0
    const int pp = lane >> 2;        // this thread's point (epilogue)

    const uint32_t mbarF = sbase + OFF_MBAR;
    const uint32_t mbarE = sbase + OFF_MBAR + 24;

    if (tid == 0) {
        #pragma unroll
        for (int i = 0; i < 3; i++) {
            MBAR_INIT(mbarF + (uint32_t)i * 8, 1u);
            MBAR_INIT(mbarE + (uint32_t)i * 8, 8u);
        }
    }
    __syncthreads();

    // distributed initial fills: chunk 0 -> warp 0, chunk 1 -> warp 1
    if (lane == 0 && wid == 0) issue_fill(sbase, 0);
    if (lane == 0 && wid == 1) issue_fill(sbase, 1);

    // ---------------- layer 0: (4 -> 256) scalar -> A' row nn ----------------
    // row within A' column: m = ch*8 + p
    {
        const float w0 = W0[nn], w1 = W0[256 + nn], w2 = W0[512 + nn], w3 = W0[768 + nn];
        const float bb = b0[nn];
        // vectorized input loads (fallback to scalar near the tail)
        float xv[NPTS], yv[NPTS], tv[NPTS], nv[NPTS];
        if (base + NPTS <= N) {
            const float4 x0 = *reinterpret_cast<const float4*>(&x[base]);
            const float4 x1 = *reinterpret_cast<const float4*>(&x[base + 4]);
            const float4 y0 = *reinterpret_cast<const float4*>(&y[base]);
            const float4 y1 = *reinterpret_cast<const float4*>(&y[base + 4]);
            const float4 t0 = *reinterpret_cast<const float4*>(&t[base]);
            const float4 t1 = *reinterpret_cast<const float4*>(&t[base + 4]);
            const float4 n0v = *reinterpret_cast<const float4*>(&nu[base]);
            const float4 n1v = *reinterpret_cast<const float4*>(&nu[base + 4]);
            xv[0]=x0.x; xv[1]=x0.y; xv[2]=x0.z; xv[3]=x0.w; xv[4]=x1.x; xv[5]=x1.y; xv[6]=x1.z; xv[7]=x1.w;
            yv[0]=y0.x; yv[1]=y0.y; yv[2]=y0.z; yv[3]=y0.w; yv[4]=y1.x; yv[5]=y1.y; yv[6]=y1.z; yv[7]=y1.w;
            tv[0]=t0.x; tv[1]=t0.y; tv[2]=t0.z; tv[3]=t0.w; tv[4]=t1.x; tv[5]=t1.y; tv[6]=t1.z; tv[7]=t1.w;
            nv[0]=n0v.x; nv[1]=n0v.y; nv[2]=n0v.z; nv[3]=n0v.w; nv[4]=n1v.x; nv[5]=n1v.y; nv[6]=n1v.z; nv[7]=n1v.w;
        } else {
            #pragma unroll
            for (int p = 0; p < NPTS; p++) {
                int idx = base + p; if (idx >= N) idx = N - 1;
                xv[p] = x[idx]; yv[p] = y[idx]; tv[p] = t[idx]; nv[p] = nu[idx];
            }
        }
        float o[6][NPTS];
        #pragma unroll
        for (int p = 0; p < NPTS; p++) {
            const float xs = xv[p];
            const float ys = yv[p];
            const float ts = 2.0f * tv[p] - 1.0f;
            const float ns = 2.0f * (nv[p] - 0.01f) * (1.0f / 0.09f) - 1.0f;
            const float z  = fmaf(xs, w0, fmaf(ys, w1, fmaf(ts, w2, fmaf(ns, w3, bb))));
            const float zx = w0, zy = w1, zt = 2.0f * w2;
            float s, sp, spp; swish_derivs(z, s, sp, spp);
            o[0][p] = s;
            o[1][p] = sp * zx;
            o[2][p] = sp * zy;
            o[3][p] = sp * zt;
            o[4][p] = spp * zx * zx;
            o[5][p] = spp * zy * zy;
        }
        uint32_t h32[24], l32[24];
        #pragma unroll
        for (int ch = 0; ch < 6; ch++)
            #pragma unroll
            for (int q = 0; q < 4; q++)
                split_pack(o[ch][2 * q], o[ch][2 * q + 1], h32[ch * 4 + q], l32[ch * 4 + q]);
        uint4* dh = reinterpret_cast<uint4*>(sm + OFF_AHI + nn * ASTR_T);
        uint4* dl = reinterpret_cast<uint4*>(sm + OFF_ALO + nn * ASTR_T);
        #pragma unroll
        for (int j = 0; j < 6; j++) {
            dh[j] = make_uint4(h32[4*j], h32[4*j+1], h32[4*j+2], h32[4*j+3]);
            dl[j] = make_uint4(l32[4*j], l32[4*j+1], l32[4*j+2], l32[4*j+3]);
        }
    }
    __syncthreads();

    // final-layer partial accumulators (used at L==2)
    float part[12];   // [ch][uv]
    #pragma unroll
    for (int r = 0; r < 12; r++) part[r] = 0.0f;

    // ---------------- 3 hidden layers: bf16-split GEMM + register swish -----
    #pragma unroll 1
    for (int L = 0; L < 3; L++) {
        const float* __restrict__ bptr = (L == 0) ? b1 : (L == 1) ? b2 : b3;

        float acc[3][4][4];
        #pragma unroll
        for (int m = 0; m < 3; m++)
            #pragma unroll
            for (int nt = 0; nt < 4; nt++)
                #pragma unroll
                for (int r = 0; r < 4; r++) acc[m][nt][r] = 0.0f;

        #pragma unroll 1
        for (int c = 0; c < 16; c++) {
            const int g = L * 16 + c;
            // distributed producer: chunk g+2 is issued by warp (g+2)&7
            if (lane == 0 && g + 2 < 48 && wid == ((g + 2) & 7)) issue_fill(sbase, g + 2);

            MBAR_WAIT(mbarF + (uint32_t)(g % 3) * 8, (uint32_t)((g / 3) & 1));

            const uint32_t bufb = sbase + OFF_B + (uint32_t)(g % 3) * BUF_BYTES;

            uint32_t Bh[8], Bl[8];
            #pragma unroll
            for (int q = 0; q < 2; q++) {
                const uint32_t roff = (uint32_t)(lane & 15) * BSTR
                                    + (uint32_t)(n0 + q * 16 + (lane >> 4) * 8) * 2;
                LDSM4T(Bh[q * 4], Bh[q * 4 + 1], Bh[q * 4 + 2], Bh[q * 4 + 3], bufb + roff);
                LDSM4T(Bl[q * 4], Bl[q * 4 + 1], Bl[q * 4 + 2], Bl[q * 4 + 3], bufb + BSPL + roff);
            }
            if (lane == 0) MBAR_ARRIVE(mbarE + (uint32_t)(g % 3) * 8);

            uint32_t Ah[3][4];
            uint32_t aroff[3];
            const uint32_t krow = (uint32_t)(c * 16 + (lane & 7) + ((lane >> 4) << 3));
            const uint32_t mcol = (uint32_t)(((lane >> 3) & 1) * 8) * 2;
            #pragma unroll
            for (int m = 0; m < 3; m++) {
                aroff[m] = krow * ASTR_T + (uint32_t)(m * 16) * 2 + mcol;
                LDSM4T(Ah[m][0], Ah[m][1], Ah[m][2], Ah[m][3], sbase + OFF_AHI + aroff[m]);
            }
            #pragma unroll
            for (int m = 0; m < 3; m++)
                #pragma unroll
                for (int nt = 0; nt < 4; nt++)
                    MMA_BF16(acc[m][nt], Ah[m][0], Ah[m][1], Ah[m][2], Ah[m][3],
                             Bh[nt * 2], Bh[nt * 2 + 1]);
            #pragma unroll
            for (int m = 0; m < 3; m++)
                #pragma unroll
                for (int nt = 0; nt < 4; nt++)
                    MMA_BF16(acc[m][nt], Ah[m][0], Ah[m][1], Ah[m][2], Ah[m][3],
                             Bl[nt * 2], Bl[nt * 2 + 1]);
            uint32_t Al[3][4];
            #pragma unroll
            for (int m = 0; m < 3; m++)
                LDSM4T(Al[m][0], Al[m][1], Al[m][2], Al[m][3], sbase + OFF_ALO + aroff[m]);
            #pragma unroll
            for (int m = 0; m < 3; m++)
                #pragma unroll
                for (int nt = 0; nt < 4; nt++)
                    MMA_BF16(acc[m][nt], Al[m][0], Al[m][1], Al[m][2], Al[m][3],
                             Bh[nt * 2], Bh[nt * 2 + 1]);
        }
        __syncthreads();   // all warps done reading A' before anyone rewrites it

        // ---- register epilogue: swish chain straight from accumulators ----
        // thread owns point pp, cols k = n0 + nt*8 + (lane&3)*2 + j
        #pragma unroll
        for (int nt = 0; nt < 4; nt++) {
            const int k0 = n0 + nt * 8 + (lane & 3) * 2;
            const float2 bv = *reinterpret_cast<const float2*>(&bptr[k0]);
            #pragma unroll
            for (int j = 0; j < 2; j++) {
                const int k = k0 + j;
                const float z   = acc[0][nt][j] + (j ? bv.y : bv.x);
                const float zx  = acc[0][nt][2 + j];
                const float zy  = acc[1][nt][j];
                const float zt  = acc[1][nt][2 + j];
                const float zxx = acc[2][nt][j];
                const float zyy = acc[2][nt][2 + j];
                float s, sp, spp; swish_derivs(z, s, sp, spp);
                const float o0 = s;
                const float o1 = sp * zx;
                const float o2 = sp * zy;
                const float o3 = sp * zt;
                const float o4 = fmaf(spp, zx * zx, sp * zxx);
                const float o5 = fmaf(spp, zy * zy, sp * zyy);
                if (L < 2) {
                    storeA1(sm, k, pp, 0, o0);
                    storeA1(sm, k, pp, 1, o1);
                    storeA1(sm, k, pp, 2, o2);
                    storeA1(sm, k, pp, 3, o3);
                    storeA1(sm, k, pp, 4, o4);
                    storeA1(sm, k, pp, 5, o5);
                } else {
                    // final layer: accumulate partial dots with W4 directly
                    const float2 w = *reinterpret_cast<const float2*>(&W4[2 * k]);
                    part[0]  = fmaf(o0, w.x, part[0]);   part[1]  = fmaf(o0, w.y, part[1]);
                    part[2]  = fmaf(o1, w.x, part[2]);   part[3]  = fmaf(o1, w.y, part[3]);
                    part[4]  = fmaf(o2, w.x, part[4]);   part[5]  = fmaf(o2, w.y, part[5]);
                    part[6]  = fmaf(o3, w.x, part[6]);   part[7]  = fmaf(o3, w.y, part[7]);
                    part[8]  = fmaf(o4, w.x, part[8]);   part[9]  = fmaf(o4, w.y, part[9]);
                    part[10] = fmaf(o5, w.x, part[10]);  part[11] = fmaf(o5, w.y, part[11]);
                }
            }
        }
        __syncthreads();   // A' writes visible (L<2); buffers reusable as scratch (L==2)
    }

    // ---------------- final reduction: quad shuffles + smem ------------------
    #pragma unroll
    for (int r = 0; r < 12; r++) {
        part[r] += __shfl_xor_sync(0xffffffffu, part[r], 1);
        part[r] += __shfl_xor_sync(0xffffffffu, part[r], 2);
    }
    float* red = reinterpret_cast<float*>(sm + OFF_RED);   // [8 warps][8 pts][12]
    if ((lane & 3) == 0) {
        float* dst = red + (wid * 8 + pp) * 12;
        #pragma unroll
        for (int r = 0; r < 12; r++) dst[r] = part[r];
    }
    __syncthreads();

    if (tid < 96) {
        const int p = tid / 12, r = tid % 12;
        float s = 0.0f;
        #pragma unroll
        for (int w = 0; w < 8; w++) s += red[(w * 8 + p) * 12 + r];
        red[768 + p * 12 + r] = s;
    }
    __syncthreads();

    if (tid < NPTS) {
        const int idx = base + tid;
        if (idx < N) {
            const float* rp = red + 768 + tid * 12;
            const float u   = rp[0] + b4[0];
            const float v   = rp[1] + b4[1];
            const float u_x = rp[2],  v_x = rp[3];
            const float u_y = rp[4],  v_y = rp[5];
            const float u_t = rp[6],  v_t = rp[7];
            const float uxx = rp[8],  vxx = rp[9];
            const float uyy = rp[10], vyy = rp[11];
            const float nv = nu[idx];
            out[idx * 2 + 0] = u_t + u * u_x + v * u_y - nv * (uxx + uyy);
            out[idx * 2 + 1] = v_t + u * v_x + v * v_y - nv * (vxx + vyy);
        }
    }
}

extern "C" void kernel_launch(void* const* d_in, const int* in_sizes, int n_in,
                              void* d_out, int out_size) {
    const float* x  = (const float*)d_in[0];
    const float* y  = (const float*)d_in[1];
    const float* t  = (const float*)d_in[2];
    const float* nu = (const float*)d_in[3];
    const float* W0 = (const float*)d_in[4];
    const float* b0 = (const float*)d_in[5];
    const float* W1 = (const float*)d_in[6];
    const float* b1 = (const float*)d_in[7];
    const float* W2 = (const float*)d_in[8];
    const float* b2 = (const float*)d_in[9];
    const float* W3 = (const float*)d_in[10];
    const float* b3 = (const float*)d_in[11];
    const float* W4 = (const float*)d_in[12];
    const float* b4 = (const float*)d_in[13];
    float* out = (float*)d_out;

    const int N = in_sizes[0];

    cudaFuncSetAttribute(pinn_mma_kernel, cudaFuncAttributeMaxDynamicSharedMemorySize, SMEM_BYTES);

    prep_kernel<<<(3 * 65536 + 255) / 256, 256>>>(W1, W2, W3);

    const int blocks = (N + NPTS - 1) / NPTS;
    pinn_mma_kernel<<<blocks, TPB, SMEM_BYTES>>>(x, y, t, nu, W0, b0,
                                                 b1, b2, b3, W4, b4, out, N);
}